// round 6
// baseline (speedup 1.0000x reference)
#include <cuda_runtime.h>

// E[b] = sum over strict-lower-tri pairs (i,j) (row-major flat order):
//          decompFE_flat[b,p] * rsqrt(|coords[b,i]-coords[b,j]|^2)
//
// BPB=2 batches/block -> grid=1024 blocks: single wave at ~8 blocks/SM,
// ~55 warps/SM (~86% occ) to hide LDG latency. jblk-major with lane-resident
// j coords; float4-padded smem for 1-LDS.128 i-coord broadcasts.

#define BATCH   2048
#define NATOMS  100
#define NC2     4950
#define TPB     256
#define NWARPS  (TPB / 32)
#define BPB     2

__global__ __launch_bounds__(TPB, 8)
void eij_kernel(const float* __restrict__ coords,
                const float* __restrict__ flat,
                float* __restrict__ out)
{
    __shared__ float sc[BPB][NATOMS * 4];       // atom*4 + {x,y,z,pad}
    __shared__ float warp_part[BPB][NWARPS];

    const int b0   = blockIdx.x * BPB;
    const int t    = threadIdx.x;
    const int lane = t & 31;
    const int wid  = t >> 5;

    // stage coords, padded to float4 per atom
    #pragma unroll
    for (int q = 0; q < BPB; ++q) {
        const float* cb = coords + (size_t)(b0 + q) * (NATOMS * 3);
        for (int k = t; k < NATOMS * 3; k += TPB)
            sc[q][(k / 3) * 4 + (k % 3)] = cb[k];
    }
    __syncthreads();

    const float* fb0 = flat + (size_t)b0 * NC2;

    float acc[BPB];
    #pragma unroll
    for (int q = 0; q < BPB; ++q) acc[q] = 0.0f;

    #pragma unroll
    for (int jb = 0; jb < 4; ++jb) {
        const int jbase = jb * 32;
        const int j = jbase + lane;

        float xj[BPB], yj[BPB], zj[BPB];
        #pragma unroll
        for (int q = 0; q < BPB; ++q) {
            xj[q] = yj[q] = zj[q] = 0.0f;
            if (j < NATOMS) {
                const float4 cj = *(const float4*)&sc[q][j * 4];
                xj[q] = cj.x; yj[q] = cj.y; zj[q] = cj.z;
            }
        }

        // ---- partial (diagonal) rows: i in [jbase+1, jbase+32], predicated ----
        for (int i = jbase + 1 + wid; i <= jbase + 32 && i < NATOMS; i += NWARPS) {
            const int  off   = i * (i - 1) / 2 + jbase + lane;
            const bool valid = lane < (i - jbase);
            #pragma unroll
            for (int q = 0; q < BPB; ++q) {
                float v = 0.0f;
                if (valid) v = __ldcs(fb0 + (size_t)q * NC2 + off);

                const float4 ci = *(const float4*)&sc[q][i * 4];
                float dx = ci.x - xj[q], dy = ci.y - yj[q], dz = ci.z - zj[q];
                float r2 = fmaf(dx, dx, fmaf(dy, dy, dz * dz));
                if (valid) acc[q] = fmaf(v, rsqrtf(r2), acc[q]);
            }
        }

        // ---- full rows: i in [jbase+33, 99], unpredicated ----
        #pragma unroll 4
        for (int i = jbase + 33 + wid; i < NATOMS; i += NWARPS) {
            const int off = i * (i - 1) / 2 + jbase + lane;
            #pragma unroll
            for (int q = 0; q < BPB; ++q) {
                float v = __ldcs(fb0 + (size_t)q * NC2 + off);

                const float4 ci = *(const float4*)&sc[q][i * 4];
                float dx = ci.x - xj[q], dy = ci.y - yj[q], dz = ci.z - zj[q];
                float r2 = fmaf(dx, dx, fmaf(dy, dy, dz * dz));
                acc[q] = fmaf(v, rsqrtf(r2), acc[q]);
            }
        }
    }

    // ---- reductions ----
    #pragma unroll
    for (int q = 0; q < BPB; ++q) {
        float a = acc[q];
        #pragma unroll
        for (int off = 16; off > 0; off >>= 1)
            a += __shfl_down_sync(0xFFFFFFFFu, a, off);
        if (lane == 0) warp_part[q][wid] = a;
    }
    __syncthreads();

    if (wid == 0 && lane < NWARPS) {
        #pragma unroll
        for (int q = 0; q < BPB; ++q) {
            float s = warp_part[q][lane];
            #pragma unroll
            for (int off = NWARPS / 2; off > 0; off >>= 1)
                s += __shfl_down_sync(0xFFu, s, off);
            if (lane == 0) out[b0 + q] = s;
        }
    }
}

extern "C" void kernel_launch(void* const* d_in, const int* in_sizes, int n_in,
                              void* d_out, int out_size)
{
    const float* coords = (const float*)d_in[0];   // [2048, 100, 3]
    const float* flat   = (const float*)d_in[1];   // [2048, 4950]
    float* out          = (float*)d_out;           // [2048, 1]

    eij_kernel<<<BATCH / BPB, TPB>>>(coords, flat, out);
}